// round 2
// baseline (speedup 1.0000x reference)
#include <cuda_runtime.h>
#include <math.h>

#define NN   400
#define FF   240
#define CC   32
#define LL   1440
#define JB_T 13     // ceil(400/32) j-tiles
#define IB_T 25     // 400/16 i-tiles
#define TI   16     // rows per block in pair kernel

// ---------------- scratch (device globals; no allocation) ----------------
__device__ float g_Pi[NN * CC];
__device__ float g_Pj[NN * CC];
__device__ float g_eT[NN * NN];
__device__ float g_e1[NN * NN];
__device__ float g_aggIpart[JB_T * NN * CC];
__device__ float g_aggJpart[IB_T * NN * CC];
__device__ float g_aggI[NN * CC];
__device__ float g_aggJ[NN * CC];
__device__ float g_x1[NN * FF];
__device__ float g_x2[NN * FF];

// ---------------- Pi/Pj precompute: Pi = x @ sw[0:240] + sb, Pj = x @ sw[240:480]
__global__ void pre_kernel(const float* __restrict__ x,
                           const float* __restrict__ sw,
                           const float* __restrict__ sb,
                           float* __restrict__ Pi, float* __restrict__ Pj) {
    int i = blockIdx.x;
    int t = threadIdx.x;          // 64 threads
    int c = t & 31, half = t >> 5;
    __shared__ float sx[FF];
    for (int k = t; k < FF; k += 64) sx[k] = x[i * FF + k];
    __syncthreads();
    const float* w = sw + half * FF * CC + c;
    float acc = 0.f;
#pragma unroll 8
    for (int k = 0; k < FF; k++) acc = fmaf(sx[k], w[k * CC], acc);
    if (half == 0) Pi[i * CC + c] = acc + sb[c];
    else           Pj[i * CC + c] = acc;
}

// ---------------- tiled transpose (400x400) ----------------
__global__ void transpose_kernel(const float* __restrict__ in, float* __restrict__ out) {
    __shared__ float tile[32][33];
    int x0 = blockIdx.x * 32, y0 = blockIdx.y * 32;
    int tx = threadIdx.x, ty = threadIdx.y;   // (32,8)
    for (int r = ty; r < 32; r += 8) {
        int row = y0 + r, col = x0 + tx;
        if (row < NN && col < NN) tile[r][tx] = in[row * NN + col];
    }
    __syncthreads();
    for (int r = ty; r < 32; r += 8) {
        int row = x0 + r, col = y0 + tx;
        if (row < NN && col < NN) out[row * NN + col] = tile[tx][r];
    }
}

// ---------------- fused pair kernel ----------------
// grid (JB_T, IB_T), block 256. lane -> j column, warp -> i rows (w, w+8).
__global__ __launch_bounds__(256)
void pair_kernel(const float* __restrict__ a, const float* __restrict__ e,
                 const float* __restrict__ eT,
                 const float* __restrict__ Pi, const float* __restrict__ Pj,
                 const float* __restrict__ sw,
                 const float* __restrict__ aiw, const float* __restrict__ aib,
                 const float* __restrict__ ajw, const float* __restrict__ ajb,
                 const float* __restrict__ ew,  const float* __restrict__ eb,
                 float* __restrict__ eout, int write_eout,
                 float* __restrict__ aggIpart, float* __restrict__ aggJpart) {
    int jb = blockIdx.x, ib = blockIdx.y;
    int t = threadIdx.x;
    int w = t >> 5, lane = t & 31;
    int j = jb * 32 + lane;
    bool jok = (j < NN);

    __shared__ float  sPi[TI][CC];
    __shared__ float4 sPack[CC];        // {sw480, sw481, aiw, ajw}
    __shared__ float  sew[CC];
    __shared__ float  sT[8][32 * 33];   // per-warp transpose scratch

    if (t < CC) {
        sPack[t] = make_float4(sw[480 * CC + t], sw[481 * CC + t], aiw[t], ajw[t]);
        sew[t] = ew[t];
    }
    for (int idx = t; idx < TI * CC; idx += 256) {
        int il = idx >> 5, c = idx & 31;
        sPi[il][c] = Pi[(ib * TI + il) * CC + c];
    }

    float pj[CC];
    if (jok) {
        const float4* p4 = reinterpret_cast<const float4*>(Pj + j * CC);
#pragma unroll
        for (int k = 0; k < CC / 4; k++) {
            float4 v = p4[k];
            pj[4 * k] = v.x; pj[4 * k + 1] = v.y; pj[4 * k + 2] = v.z; pj[4 * k + 3] = v.w;
        }
    } else {
#pragma unroll
        for (int c = 0; c < CC; c++) pj[c] = 0.f;
    }

    float aggj[CC];
#pragma unroll
    for (int c = 0; c < CC; c++) aggj[c] = 0.f;
    float aibv = aib[0], ajbv = ajb[0], ebv = eb[0];
    __syncthreads();

    float* myT = sT[w];
    for (int ii = w; ii < TI; ii += 8) {
        int i = ib * TI + ii;
        float aij = jok ? a[i * NN + j]  : 0.f;
        float eij = jok ? e[i * NN + j]  : 0.f;
        float eji = jok ? eT[i * NN + j] : 0.f;
        float d1 = aibv, d2 = ajbv, d3 = ebv;
        float s[CC];
#pragma unroll
        for (int c = 0; c < CC; c++) {
            float4 wp = sPack[c];
            float lin = sPi[ii][c] + pj[c] + eij * wp.x + eji * wp.y;
            float sc = fmaxf(lin, 0.f) * aij;
            s[c] = sc;
            d1 = fmaf(sc, wp.z, d1);
            d2 = fmaf(sc, wp.w, d2);
            d3 = fmaf(sc, sew[c], d3);
        }
        float atti = 1.f / (1.f + __expf(-d1));
        float attj = 1.f / (1.f + __expf(-d2));
        if (write_eout && jok) eout[i * NN + j] = d3;
#pragma unroll
        for (int c = 0; c < CC; c++) {
            aggj[c] = fmaf(attj, s[c], aggj[c]);
            myT[lane * 33 + c] = atti * s[c];
        }
        __syncwarp();
        float acc = 0.f;
#pragma unroll
        for (int r = 0; r < 32; r++) acc += myT[r * 33 + lane];
        aggIpart[(jb * NN + i) * CC + lane] = acc;
        __syncwarp();
    }

    // cross-warp agg_j: each warp dumps regs into its own slab, then block-reduce
    __syncthreads();   // all warps done with sT pair usage
#pragma unroll
    for (int c = 0; c < CC; c++) myT[lane * 33 + c] = aggj[c];
    __syncthreads();
    for (int idx = t; idx < 32 * CC; idx += 256) {
        int jl = idx >> 5, c = idx & 31;
        float v = 0.f;
#pragma unroll
        for (int ww = 0; ww < 8; ww++) v += sT[ww][jl * 33 + c];
        int jg = jb * 32 + jl;
        if (jg < NN) aggJpart[(ib * NN + jg) * CC + c] = v;
    }
}

// ---------------- reduce partial slabs ----------------
__global__ void reduce_agg_kernel() {
    int idx = blockIdx.x * 256 + threadIdx.x;
    if (idx >= NN * CC) return;
    float ai = 0.f;
#pragma unroll
    for (int p = 0; p < JB_T; p++) ai += g_aggIpart[p * NN * CC + idx];
    g_aggI[idx] = ai;
    float aj = 0.f;
#pragma unroll
    for (int p = 0; p < IB_T; p++) aj += g_aggJpart[p * NN * CC + idx];
    g_aggJ[idx] = aj;
}

// ---------------- node model: xout = [x, aggI, aggJ] @ nw + nb ----------------
__global__ void node_kernel(const float* __restrict__ x,
                            const float* __restrict__ nw, const float* __restrict__ nb,
                            float* __restrict__ xout) {
    int i = blockIdx.x;
    int f = threadIdx.x;   // 240
    __shared__ float row[304];
    row[f] = x[i * FF + f];
    if (f < 32)       row[240 + f]        = g_aggI[i * CC + f];
    else if (f < 64)  row[272 + (f - 32)] = g_aggJ[i * CC + (f - 32)];
    __syncthreads();
    float acc = nb[f];
#pragma unroll 8
    for (int k = 0; k < 304; k++) acc = fmaf(row[k], nw[k * FF + f], acc);
    xout[i * FF + f] = acc;
}

// ---------------- dense head: out = x2 @ dw + db ----------------
__global__ void dense_kernel(const float* __restrict__ x,
                             const float* __restrict__ dw, const float* __restrict__ db,
                             float* __restrict__ out) {
    int i = blockIdx.x;
    int l = blockIdx.y * 480 + threadIdx.x;
    __shared__ float row[FF];
    if (threadIdx.x < FF) row[threadIdx.x] = x[i * FF + threadIdx.x];
    __syncthreads();
    float acc = db[l];
#pragma unroll 8
    for (int k = 0; k < FF; k++) acc = fmaf(row[k], dw[k * LL + l], acc);
    out[i * LL + l] = acc;
}

// ---------------- launch ----------------
extern "C" void kernel_launch(void* const* d_in, const int* in_sizes, int n_in,
                              void* d_out, int out_size) {
    const float* x  = (const float*)d_in[0];
    const float* a  = (const float*)d_in[1];
    const float* e  = (const float*)d_in[2];
    const float* c1_sw  = (const float*)d_in[3];
    const float* c1_sb  = (const float*)d_in[4];
    const float* c1_aiw = (const float*)d_in[5];
    const float* c1_aib = (const float*)d_in[6];
    const float* c1_ajw = (const float*)d_in[7];
    const float* c1_ajb = (const float*)d_in[8];
    const float* c1_nw  = (const float*)d_in[9];
    const float* c1_nb  = (const float*)d_in[10];
    const float* c1_ew  = (const float*)d_in[11];
    const float* c1_eb  = (const float*)d_in[12];
    const float* c2_sw  = (const float*)d_in[13];
    const float* c2_sb  = (const float*)d_in[14];
    const float* c2_aiw = (const float*)d_in[15];
    const float* c2_aib = (const float*)d_in[16];
    const float* c2_ajw = (const float*)d_in[17];
    const float* c2_ajb = (const float*)d_in[18];
    const float* c2_nw  = (const float*)d_in[19];
    const float* c2_nb  = (const float*)d_in[20];
    const float* c2_ew  = (const float*)d_in[21];
    const float* c2_eb  = (const float*)d_in[22];
    const float* dw     = (const float*)d_in[23];
    const float* db     = (const float*)d_in[24];
    float* out = (float*)d_out;

    float *pPi, *pPj, *pET, *pE1, *pAIp, *pAJp, *pX1, *pX2;
    cudaGetSymbolAddress((void**)&pPi,  g_Pi);
    cudaGetSymbolAddress((void**)&pPj,  g_Pj);
    cudaGetSymbolAddress((void**)&pET,  g_eT);
    cudaGetSymbolAddress((void**)&pE1,  g_e1);
    cudaGetSymbolAddress((void**)&pAIp, g_aggIpart);
    cudaGetSymbolAddress((void**)&pAJp, g_aggJpart);
    cudaGetSymbolAddress((void**)&pX1,  g_x1);
    cudaGetSymbolAddress((void**)&pX2,  g_x2);

    dim3 tgrid(JB_T, JB_T), tblk(32, 8);
    dim3 pgrid(JB_T, IB_T);

    // ---- layer 1 ----
    pre_kernel<<<NN, 64>>>(x, c1_sw, c1_sb, pPi, pPj);
    transpose_kernel<<<tgrid, tblk>>>(e, pET);
    pair_kernel<<<pgrid, 256>>>(a, e, pET, pPi, pPj, c1_sw,
                                c1_aiw, c1_aib, c1_ajw, c1_ajb, c1_ew, c1_eb,
                                pE1, 1, pAIp, pAJp);
    reduce_agg_kernel<<<(NN * CC + 255) / 256, 256>>>();
    node_kernel<<<NN, FF>>>(x, c1_nw, c1_nb, pX1);

    // ---- layer 2 (e_out unused downstream -> skipped) ----
    pre_kernel<<<NN, 64>>>(pX1, c2_sw, c2_sb, pPi, pPj);
    transpose_kernel<<<tgrid, tblk>>>(pE1, pET);
    pair_kernel<<<pgrid, 256>>>(a, pE1, pET, pPi, pPj, c2_sw,
                                c2_aiw, c2_aib, c2_ajw, c2_ajb, c2_ew, c2_eb,
                                nullptr, 0, pAIp, pAJp);
    reduce_agg_kernel<<<(NN * CC + 255) / 256, 256>>>();
    node_kernel<<<NN, FF>>>(pX1, c2_nw, c2_nb, pX2);

    // ---- dense head ----
    dim3 dgrid(NN, LL / 480);
    dense_kernel<<<dgrid, 480>>>(pX2, dw, db, out);
}

// round 3
// speedup vs baseline: 1.1561x; 1.1561x over previous
#include <cuda_runtime.h>
#include <math.h>

#define NN   400
#define FF   240
#define CC   32
#define LL   1440
#define JB_T 13     // ceil(400/32) j-tiles
#define IB_T 25     // 400/16 i-tiles
#define TI   16     // i rows per pair-kernel block

// ---------------- scratch (device globals; no allocation) ----------------
__device__ float g_Pi[NN * CC];
__device__ float g_Pj[NN * CC];
__device__ float g_e1[NN * NN];
__device__ float g_aggIpart[JB_T * NN * CC];
__device__ float g_aggJpart[IB_T * NN * CC];
__device__ float g_x1[NN * FF];
__device__ float g_x2[NN * FF];

// ---------------- Pi/Pj precompute: Pi = x @ sw[0:240] + sb, Pj = x @ sw[240:480]
// grid 25 (16 rows/block), block 256: c = t&31, half = (t>>5)&1, q = t>>6 (4 rows each)
__global__ __launch_bounds__(256)
void pre_kernel(const float* __restrict__ x,
                const float* __restrict__ sw,
                const float* __restrict__ sb,
                float* __restrict__ Pi, float* __restrict__ Pj) {
    int b = blockIdx.x, t = threadIdx.x;
    int c = t & 31, half = (t >> 5) & 1, q = t >> 6;
    __shared__ float sx[16][FF];
    for (int idx = t; idx < 16 * FF; idx += 256) {
        int r = idx / FF, k = idx % FF;
        sx[r][k] = x[(b * 16 + r) * FF + k];
    }
    __syncthreads();
    const float* w = sw + half * FF * CC + c;
    float acc[4] = {0.f, 0.f, 0.f, 0.f};
    for (int k = 0; k < FF; k += 4) {
        float w0 = w[k * CC], w1 = w[(k + 1) * CC], w2 = w[(k + 2) * CC], w3 = w[(k + 3) * CC];
#pragma unroll
        for (int r = 0; r < 4; r++) {
            float4 xv = *reinterpret_cast<const float4*>(&sx[q * 4 + r][k]);
            acc[r] = fmaf(xv.x, w0, fmaf(xv.y, w1, fmaf(xv.z, w2, fmaf(xv.w, w3, acc[r]))));
        }
    }
    float bias = sb[c];
#pragma unroll
    for (int r = 0; r < 4; r++) {
        int i = b * 16 + q * 4 + r;
        if (half == 0) Pi[i * CC + c] = acc[r] + bias;
        else           Pj[i * CC + c] = acc[r];
    }
}

// ---------------- fused pair kernel (with in-block e-transpose) ----------------
// grid (JB_T, IB_T), block 256. lane -> j column, warp -> i rows (w, w+8).
__global__ __launch_bounds__(256)
void pair_kernel(const float* __restrict__ a, const float* __restrict__ e,
                 const float* __restrict__ Pi, const float* __restrict__ Pj,
                 const float* __restrict__ sw,
                 const float* __restrict__ aiw, const float* __restrict__ aib,
                 const float* __restrict__ ajw, const float* __restrict__ ajb,
                 const float* __restrict__ ew,  const float* __restrict__ eb,
                 float* __restrict__ eout, int write_eout,
                 float* __restrict__ aggIpart, float* __restrict__ aggJpart) {
    int jb = blockIdx.x, ib = blockIdx.y;
    int t = threadIdx.x;
    int w = t >> 5, lane = t & 31;
    int j = jb * 32 + lane;
    bool jok = (j < NN);

    __shared__ float  sPi[TI][CC];
    __shared__ float4 sPack[CC];        // {sw480, sw481, aiw, ajw}
    __shared__ float  sew[CC];
    __shared__ float  sET[TI * 33];     // e^T tile: sET[ii*33 + jl] = e[j, i]
    __shared__ float  sT[8][32 * 33];   // per-warp transpose scratch

    if (t < CC) {
        sPack[t] = make_float4(sw[480 * CC + t], sw[481 * CC + t], aiw[t], ajw[t]);
        sew[t] = ew[t];
    }
    for (int idx = t; idx < TI * CC; idx += 256) {
        int il = idx >> 5, c = idx & 31;
        sPi[il][c] = Pi[(ib * TI + il) * CC + c];
    }
    // load + transpose the e[j, i] tile (32 j rows x 16 i cols)
    for (int idx = t; idx < 32 * TI; idx += 256) {
        int jl = idx >> 4, il = idx & 15;
        int jg = jb * 32 + jl;
        sET[il * 33 + jl] = (jg < NN) ? e[jg * NN + ib * TI + il] : 0.f;
    }

    float pj[CC];
    if (jok) {
        const float4* p4 = reinterpret_cast<const float4*>(Pj + j * CC);
#pragma unroll
        for (int k = 0; k < CC / 4; k++) {
            float4 v = p4[k];
            pj[4 * k] = v.x; pj[4 * k + 1] = v.y; pj[4 * k + 2] = v.z; pj[4 * k + 3] = v.w;
        }
    } else {
#pragma unroll
        for (int c = 0; c < CC; c++) pj[c] = 0.f;
    }

    float aggj[CC];
#pragma unroll
    for (int c = 0; c < CC; c++) aggj[c] = 0.f;
    float aibv = aib[0], ajbv = ajb[0], ebv = eb[0];
    __syncthreads();

    float* myT = sT[w];
    for (int ii = w; ii < TI; ii += 8) {
        int i = ib * TI + ii;
        float aij = jok ? a[i * NN + j] : 0.f;
        float eij = jok ? e[i * NN + j] : 0.f;
        float eji = sET[ii * 33 + lane];
        float d1 = aibv, d2 = ajbv, d3 = ebv;
        float s[CC];
#pragma unroll
        for (int c = 0; c < CC; c++) {
            float4 wp = sPack[c];
            float lin = sPi[ii][c] + pj[c] + eij * wp.x + eji * wp.y;
            float sc = fmaxf(lin, 0.f) * aij;
            s[c] = sc;
            d1 = fmaf(sc, wp.z, d1);
            d2 = fmaf(sc, wp.w, d2);
            d3 = fmaf(sc, sew[c], d3);
        }
        float atti = 1.f / (1.f + __expf(-d1));
        float attj = 1.f / (1.f + __expf(-d2));
        if (write_eout && jok) eout[i * NN + j] = d3;
#pragma unroll
        for (int c = 0; c < CC; c++) {
            aggj[c] = fmaf(attj, s[c], aggj[c]);
            myT[lane * 33 + c] = atti * s[c];
        }
        __syncwarp();
        float acc = 0.f;
#pragma unroll
        for (int r = 0; r < 32; r++) acc += myT[r * 33 + lane];
        aggIpart[(jb * NN + i) * CC + lane] = acc;
        __syncwarp();
    }

    // cross-warp agg_j reduce
    __syncthreads();
#pragma unroll
    for (int c = 0; c < CC; c++) myT[lane * 33 + c] = aggj[c];
    __syncthreads();
    for (int idx = t; idx < 32 * CC; idx += 256) {
        int jl = idx >> 5, c = idx & 31;
        float v = 0.f;
#pragma unroll
        for (int ww = 0; ww < 8; ww++) v += sT[ww][jl * 33 + c];
        int jg = jb * 32 + jl;
        if (jg < NN) aggJpart[(ib * NN + jg) * CC + c] = v;
    }
}

// ---------------- node model (fused partial-reduce): xout = [x, aggI, aggJ] @ nw + nb
// grid 50 (8 rows/block), block 240 (one f each), 8 accumulators/thread
#define NIT 8
__global__ __launch_bounds__(240)
void node_kernel(const float* __restrict__ x,
                 const float* __restrict__ nw, const float* __restrict__ nb,
                 const float* __restrict__ aggIpart, const float* __restrict__ aggJpart,
                 float* __restrict__ xout) {
    int b = blockIdx.x, t = threadIdx.x;
    int i0 = b * NIT;
    __shared__ float row[NIT][304];
    // phase 0: reduce partial slabs into the concat columns
    for (int idx = t; idx < NIT * CC; idx += 240) {
        int il = idx >> 5, c = idx & 31;
        int i = i0 + il;
        float ai = 0.f;
#pragma unroll
        for (int p = 0; p < JB_T; p++) ai += aggIpart[(p * NN + i) * CC + c];
        row[il][240 + c] = ai;
        float aj = 0.f;
#pragma unroll
        for (int p = 0; p < IB_T; p++) aj += aggJpart[(p * NN + i) * CC + c];
        row[il][272 + c] = aj;
    }
    for (int idx = t; idx < NIT * FF; idx += 240) {
        int il = idx / FF, k = idx % FF;
        row[il][k] = x[(i0 + il) * FF + k];
    }
    __syncthreads();
    int f = t;
    float acc[NIT];
    float bias = nb[f];
#pragma unroll
    for (int r = 0; r < NIT; r++) acc[r] = bias;
    for (int k = 0; k < 304; k += 4) {
        float w0 = nw[k * FF + f], w1 = nw[(k + 1) * FF + f];
        float w2 = nw[(k + 2) * FF + f], w3 = nw[(k + 3) * FF + f];
#pragma unroll
        for (int r = 0; r < NIT; r++) {
            float4 xv = *reinterpret_cast<const float4*>(&row[r][k]);
            acc[r] = fmaf(xv.x, w0, fmaf(xv.y, w1, fmaf(xv.z, w2, fmaf(xv.w, w3, acc[r]))));
        }
    }
#pragma unroll
    for (int r = 0; r < NIT; r++) xout[(i0 + r) * FF + f] = acc[r];
}

// ---------------- dense head: out = x2 @ dw + db ----------------
// grid (25, 3): 16 rows x 480 cols per block, block 480, 16 accumulators/thread
#define DIT 16
__global__ __launch_bounds__(480)
void dense_kernel(const float* __restrict__ x,
                  const float* __restrict__ dw, const float* __restrict__ db,
                  float* __restrict__ out) {
    int b = blockIdx.x, t = threadIdx.x;
    int i0 = b * DIT;
    int l = blockIdx.y * 480 + t;
    __shared__ float row[DIT][FF];
    for (int idx = t; idx < DIT * FF; idx += 480) {
        int il = idx / FF, k = idx % FF;
        row[il][k] = x[(i0 + il) * FF + k];
    }
    __syncthreads();
    float acc[DIT];
    float bias = db[l];
#pragma unroll
    for (int r = 0; r < DIT; r++) acc[r] = bias;
    for (int k = 0; k < FF; k += 4) {
        float w0 = dw[k * LL + l], w1 = dw[(k + 1) * LL + l];
        float w2 = dw[(k + 2) * LL + l], w3 = dw[(k + 3) * LL + l];
#pragma unroll
        for (int r = 0; r < DIT; r++) {
            float4 xv = *reinterpret_cast<const float4*>(&row[r][k]);
            acc[r] = fmaf(xv.x, w0, fmaf(xv.y, w1, fmaf(xv.z, w2, fmaf(xv.w, w3, acc[r]))));
        }
    }
#pragma unroll
    for (int r = 0; r < DIT; r++) out[(i0 + r) * LL + l] = acc[r];
}

// ---------------- launch ----------------
extern "C" void kernel_launch(void* const* d_in, const int* in_sizes, int n_in,
                              void* d_out, int out_size) {
    const float* x  = (const float*)d_in[0];
    const float* a  = (const float*)d_in[1];
    const float* e  = (const float*)d_in[2];
    const float* c1_sw  = (const float*)d_in[3];
    const float* c1_sb  = (const float*)d_in[4];
    const float* c1_aiw = (const float*)d_in[5];
    const float* c1_aib = (const float*)d_in[6];
    const float* c1_ajw = (const float*)d_in[7];
    const float* c1_ajb = (const float*)d_in[8];
    const float* c1_nw  = (const float*)d_in[9];
    const float* c1_nb  = (const float*)d_in[10];
    const float* c1_ew  = (const float*)d_in[11];
    const float* c1_eb  = (const float*)d_in[12];
    const float* c2_sw  = (const float*)d_in[13];
    const float* c2_sb  = (const float*)d_in[14];
    const float* c2_aiw = (const float*)d_in[15];
    const float* c2_aib = (const float*)d_in[16];
    const float* c2_ajw = (const float*)d_in[17];
    const float* c2_ajb = (const float*)d_in[18];
    const float* c2_nw  = (const float*)d_in[19];
    const float* c2_nb  = (const float*)d_in[20];
    const float* c2_ew  = (const float*)d_in[21];
    const float* c2_eb  = (const float*)d_in[22];
    const float* dw     = (const float*)d_in[23];
    const float* db     = (const float*)d_in[24];
    float* out = (float*)d_out;

    float *pPi, *pPj, *pE1, *pAIp, *pAJp, *pX1, *pX2;
    cudaGetSymbolAddress((void**)&pPi,  g_Pi);
    cudaGetSymbolAddress((void**)&pPj,  g_Pj);
    cudaGetSymbolAddress((void**)&pE1,  g_e1);
    cudaGetSymbolAddress((void**)&pAIp, g_aggIpart);
    cudaGetSymbolAddress((void**)&pAJp, g_aggJpart);
    cudaGetSymbolAddress((void**)&pX1,  g_x1);
    cudaGetSymbolAddress((void**)&pX2,  g_x2);

    dim3 pgrid(JB_T, IB_T);

    // ---- layer 1 ----
    pre_kernel<<<25, 256>>>(x, c1_sw, c1_sb, pPi, pPj);
    pair_kernel<<<pgrid, 256>>>(a, e, pPi, pPj, c1_sw,
                                c1_aiw, c1_aib, c1_ajw, c1_ajb, c1_ew, c1_eb,
                                pE1, 1, pAIp, pAJp);
    node_kernel<<<50, 240>>>(x, c1_nw, c1_nb, pAIp, pAJp, pX1);

    // ---- layer 2 (e_out unused downstream -> skipped) ----
    pre_kernel<<<25, 256>>>(pX1, c2_sw, c2_sb, pPi, pPj);
    pair_kernel<<<pgrid, 256>>>(a, pE1, pPi, pPj, c2_sw,
                                c2_aiw, c2_aib, c2_ajw, c2_ajb, c2_ew, c2_eb,
                                nullptr, 0, pAIp, pAJp);
    node_kernel<<<50, 240>>>(pX1, c2_nw, c2_nb, pAIp, pAJp, pX2);

    // ---- dense head ----
    dim3 dgrid(25, 3);
    dense_kernel<<<dgrid, 480>>>(pX2, dw, db, out);
}

// round 12
// speedup vs baseline: 1.8012x; 1.5580x over previous
#include <cuda_runtime.h>
#include <math.h>

#define NN   400
#define FF   240
#define CC   32
#define LL   1440
#define JB_T 13     // ceil(400/32) j-tiles
#define IB_T 25     // 400/16 i-tiles
#define TI   16     // i rows per pair-kernel block

// ---------------- scratch (device globals; no allocation) ----------------
__device__ float g_Pi[NN * CC];
__device__ float g_Pj[NN * CC];
__device__ float g_e1[NN * NN];
__device__ float g_aggIpart[JB_T * NN * CC];
__device__ float g_aggJpart[IB_T * NN * CC];
__device__ float g_x1[NN * FF];
__device__ float g_x2[NN * FF];

// ---------------- Pi/Pj precompute: Pi = x @ sw[0:240] + sb, Pj = x @ sw[240:480]
// grid 100 (4 rows/block), block 256 = 64 outputs (half,c) x 4 k-chunks (60 k each).
__global__ __launch_bounds__(256)
void pre_kernel(const float* __restrict__ x,
                const float* __restrict__ sw,
                const float* __restrict__ sb,
                float* __restrict__ Pi, float* __restrict__ Pj) {
    int b = blockIdx.x, t = threadIdx.x;
    int c = t & 31, half = (t >> 5) & 1, kq = t >> 6;   // kq in 0..3
    int i0 = b * 4;
    __shared__ float sx[4][FF];
    __shared__ float sred[4][4][64];   // [kq][row][out_id]
    for (int idx = t; idx < 4 * FF; idx += 256) {
        int r = idx / FF, k = idx % FF;
        sx[r][k] = x[(i0 + r) * FF + k];
    }
    __syncthreads();
    const float* w = sw + half * FF * CC + c;
    float acc[4] = {0.f, 0.f, 0.f, 0.f};
    int k0 = kq * 60;
#pragma unroll
    for (int kk = 0; kk < 60; kk += 4) {
        int k = k0 + kk;
        float w0 = w[k * CC], w1 = w[(k + 1) * CC], w2 = w[(k + 2) * CC], w3 = w[(k + 3) * CC];
#pragma unroll
        for (int r = 0; r < 4; r++) {
            float4 xv = *reinterpret_cast<const float4*>(&sx[r][k]);
            acc[r] = fmaf(xv.x, w0, fmaf(xv.y, w1, fmaf(xv.z, w2, fmaf(xv.w, w3, acc[r]))));
        }
    }
    int oid = half * 32 + c;
#pragma unroll
    for (int r = 0; r < 4; r++) sred[kq][r][oid] = acc[r];
    __syncthreads();
    // 256 threads = 64 outputs x 4 rows; sum over kq
    int oid2 = t & 63, r2 = t >> 6;
    float v = sred[0][r2][oid2] + sred[1][r2][oid2] + sred[2][r2][oid2] + sred[3][r2][oid2];
    int h2 = oid2 >> 5, c2 = oid2 & 31, i = i0 + r2;
    if (h2 == 0) Pi[i * CC + c2] = v + sb[c2];
    else         Pj[i * CC + c2] = v;
}

// ---------------- fused pair kernel (with in-block e-transpose) ----------------
// grid (JB_T, IB_T), block 256. lane -> j column, warp -> i rows (w, w+8).
__global__ __launch_bounds__(256)
void pair_kernel(const float* __restrict__ a, const float* __restrict__ e,
                 const float* __restrict__ Pi, const float* __restrict__ Pj,
                 const float* __restrict__ sw,
                 const float* __restrict__ aiw, const float* __restrict__ aib,
                 const float* __restrict__ ajw, const float* __restrict__ ajb,
                 const float* __restrict__ ew,  const float* __restrict__ eb,
                 float* __restrict__ eout, int write_eout,
                 float* __restrict__ aggIpart, float* __restrict__ aggJpart) {
    int jb = blockIdx.x, ib = blockIdx.y;
    int t = threadIdx.x;
    int w = t >> 5, lane = t & 31;
    int j = jb * 32 + lane;
    bool jok = (j < NN);

    __shared__ float  sPi[TI][CC];
    __shared__ float4 sPack[CC];        // {sw480, sw481, aiw, ajw}
    __shared__ float  sew[CC];
    __shared__ float  sET[TI * 33];     // e^T tile: sET[ii*33 + jl] = e[j, i]
    __shared__ float  sT[8][32 * 33];   // per-warp transpose scratch

    if (t < CC) {
        sPack[t] = make_float4(sw[480 * CC + t], sw[481 * CC + t], aiw[t], ajw[t]);
        sew[t] = ew[t];
    }
    for (int idx = t; idx < TI * CC; idx += 256) {
        int il = idx >> 5, c = idx & 31;
        sPi[il][c] = Pi[(ib * TI + il) * CC + c];
    }
    // load + transpose the e[j, i] tile (32 j rows x 16 i cols)
    for (int idx = t; idx < 32 * TI; idx += 256) {
        int jl = idx >> 4, il = idx & 15;
        int jg = jb * 32 + jl;
        sET[il * 33 + jl] = (jg < NN) ? e[jg * NN + ib * TI + il] : 0.f;
    }

    float pj[CC];
    if (jok) {
        const float4* p4 = reinterpret_cast<const float4*>(Pj + j * CC);
#pragma unroll
        for (int k = 0; k < CC / 4; k++) {
            float4 v = p4[k];
            pj[4 * k] = v.x; pj[4 * k + 1] = v.y; pj[4 * k + 2] = v.z; pj[4 * k + 3] = v.w;
        }
    } else {
#pragma unroll
        for (int c = 0; c < CC; c++) pj[c] = 0.f;
    }

    float aggj[CC];
#pragma unroll
    for (int c = 0; c < CC; c++) aggj[c] = 0.f;
    float aibv = aib[0], ajbv = ajb[0], ebv = eb[0];
    __syncthreads();

    float* myT = sT[w];
    for (int ii = w; ii < TI; ii += 8) {
        int i = ib * TI + ii;
        float aij = jok ? a[i * NN + j] : 0.f;
        float eij = jok ? e[i * NN + j] : 0.f;
        float eji = sET[ii * 33 + lane];
        float d1 = aibv, d2 = ajbv, d3 = ebv;
        float s[CC];
#pragma unroll
        for (int c = 0; c < CC; c++) {
            float4 wp = sPack[c];
            float lin = sPi[ii][c] + pj[c] + eij * wp.x + eji * wp.y;
            float sc = fmaxf(lin, 0.f) * aij;
            s[c] = sc;
            d1 = fmaf(sc, wp.z, d1);
            d2 = fmaf(sc, wp.w, d2);
            d3 = fmaf(sc, sew[c], d3);
        }
        float atti = 1.f / (1.f + __expf(-d1));
        float attj = 1.f / (1.f + __expf(-d2));
        if (write_eout && jok) eout[i * NN + j] = d3;
#pragma unroll
        for (int c = 0; c < CC; c++) {
            aggj[c] = fmaf(attj, s[c], aggj[c]);
            myT[lane * 33 + c] = atti * s[c];
        }
        __syncwarp();
        float acc = 0.f;
#pragma unroll
        for (int r = 0; r < 32; r++) acc += myT[r * 33 + lane];
        aggIpart[(jb * NN + i) * CC + lane] = acc;
        __syncwarp();
    }

    // cross-warp agg_j reduce
    __syncthreads();
#pragma unroll
    for (int c = 0; c < CC; c++) myT[lane * 33 + c] = aggj[c];
    __syncthreads();
    for (int idx = t; idx < 32 * CC; idx += 256) {
        int jl = idx >> 5, c = idx & 31;
        float v = 0.f;
#pragma unroll
        for (int ww = 0; ww < 8; ww++) v += sT[ww][jl * 33 + c];
        int jg = jb * 32 + jl;
        if (jg < NN) aggJpart[(ib * NN + jg) * CC + c] = v;
    }
}

// ---------------- node model (fused partial-reduce): xout = [x, aggI, aggJ] @ nw + nb
// grid 100 (4 rows/block), block 240 (one f each), 4 accumulators/thread
#define NIT 4
__global__ __launch_bounds__(240)
void node_kernel(const float* __restrict__ x,
                 const float* __restrict__ nw, const float* __restrict__ nb,
                 const float* __restrict__ aggIpart, const float* __restrict__ aggJpart,
                 float* __restrict__ xout) {
    int b = blockIdx.x, t = threadIdx.x;
    int i0 = b * NIT;
    __shared__ float row[NIT][304];
    // phase 0: reduce partial slabs into the concat columns
    for (int idx = t; idx < NIT * CC; idx += 240) {
        int il = idx >> 5, c = idx & 31;
        int i = i0 + il;
        float ai = 0.f;
#pragma unroll
        for (int p = 0; p < JB_T; p++) ai += aggIpart[(p * NN + i) * CC + c];
        row[il][240 + c] = ai;
        float aj = 0.f;
#pragma unroll
        for (int p = 0; p < IB_T; p++) aj += aggJpart[(p * NN + i) * CC + c];
        row[il][272 + c] = aj;
    }
    for (int idx = t; idx < NIT * FF; idx += 240) {
        int il = idx / FF, k = idx % FF;
        row[il][k] = x[(i0 + il) * FF + k];
    }
    __syncthreads();
    int f = t;
    float acc[NIT];
    float bias = nb[f];
#pragma unroll
    for (int r = 0; r < NIT; r++) acc[r] = bias;
#pragma unroll 4
    for (int k = 0; k < 304; k += 4) {
        float w0 = nw[k * FF + f], w1 = nw[(k + 1) * FF + f];
        float w2 = nw[(k + 2) * FF + f], w3 = nw[(k + 3) * FF + f];
#pragma unroll
        for (int r = 0; r < NIT; r++) {
            float4 xv = *reinterpret_cast<const float4*>(&row[r][k]);
            acc[r] = fmaf(xv.x, w0, fmaf(xv.y, w1, fmaf(xv.z, w2, fmaf(xv.w, w3, acc[r]))));
        }
    }
#pragma unroll
    for (int r = 0; r < NIT; r++) xout[(i0 + r) * FF + f] = acc[r];
}

// ---------------- dense head: out = x2 @ dw + db ----------------
// grid (50, 3): 8 rows x 480 cols per block, block 480, 8 accumulators/thread
#define DIT 8
__global__ __launch_bounds__(480)
void dense_kernel(const float* __restrict__ x,
                  const float* __restrict__ dw, const float* __restrict__ db,
                  float* __restrict__ out) {
    int b = blockIdx.x, t = threadIdx.x;
    int i0 = b * DIT;
    int l = blockIdx.y * 480 + t;
    __shared__ float row[DIT][FF];
    for (int idx = t; idx < DIT * FF; idx += 480) {
        int il = idx / FF, k = idx % FF;
        row[il][k] = x[(i0 + il) * FF + k];
    }
    __syncthreads();
    float acc[DIT];
    float bias = db[l];
#pragma unroll
    for (int r = 0; r < DIT; r++) acc[r] = bias;
#pragma unroll 4
    for (int k = 0; k < FF; k += 4) {
        float w0 = dw[k * LL + l], w1 = dw[(k + 1) * LL + l];
        float w2 = dw[(k + 2) * LL + l], w3 = dw[(k + 3) * LL + l];
#pragma unroll
        for (int r = 0; r < DIT; r++) {
            float4 xv = *reinterpret_cast<const float4*>(&row[r][k]);
            acc[r] = fmaf(xv.x, w0, fmaf(xv.y, w1, fmaf(xv.z, w2, fmaf(xv.w, w3, acc[r]))));
        }
    }
#pragma unroll
    for (int r = 0; r < DIT; r++) out[(i0 + r) * LL + l] = acc[r];
}

// ---------------- launch ----------------
extern "C" void kernel_launch(void* const* d_in, const int* in_sizes, int n_in,
                              void* d_out, int out_size) {
    const float* x  = (const float*)d_in[0];
    const float* a  = (const float*)d_in[1];
    const float* e  = (const float*)d_in[2];
    const float* c1_sw  = (const float*)d_in[3];
    const float* c1_sb  = (const float*)d_in[4];
    const float* c1_aiw = (const float*)d_in[5];
    const float* c1_aib = (const float*)d_in[6];
    const float* c1_ajw = (const float*)d_in[7];
    const float* c1_ajb = (const float*)d_in[8];
    const float* c1_nw  = (const float*)d_in[9];
    const float* c1_nb  = (const float*)d_in[10];
    const float* c1_ew  = (const float*)d_in[11];
    const float* c1_eb  = (const float*)d_in[12];
    const float* c2_sw  = (const float*)d_in[13];
    const float* c2_sb  = (const float*)d_in[14];
    const float* c2_aiw = (const float*)d_in[15];
    const float* c2_aib = (const float*)d_in[16];
    const float* c2_ajw = (const float*)d_in[17];
    const float* c2_ajb = (const float*)d_in[18];
    const float* c2_nw  = (const float*)d_in[19];
    const float* c2_nb  = (const float*)d_in[20];
    const float* c2_ew  = (const float*)d_in[21];
    const float* c2_eb  = (const float*)d_in[22];
    const float* dw     = (const float*)d_in[23];
    const float* db     = (const float*)d_in[24];
    float* out = (float*)d_out;

    float *pPi, *pPj, *pE1, *pAIp, *pAJp, *pX1, *pX2;
    cudaGetSymbolAddress((void**)&pPi,  g_Pi);
    cudaGetSymbolAddress((void**)&pPj,  g_Pj);
    cudaGetSymbolAddress((void**)&pE1,  g_e1);
    cudaGetSymbolAddress((void**)&pAIp, g_aggIpart);
    cudaGetSymbolAddress((void**)&pAJp, g_aggJpart);
    cudaGetSymbolAddress((void**)&pX1,  g_x1);
    cudaGetSymbolAddress((void**)&pX2,  g_x2);

    dim3 pgrid(JB_T, IB_T);

    // ---- layer 1 ----
    pre_kernel<<<100, 256>>>(x, c1_sw, c1_sb, pPi, pPj);
    pair_kernel<<<pgrid, 256>>>(a, e, pPi, pPj, c1_sw,
                                c1_aiw, c1_aib, c1_ajw, c1_ajb, c1_ew, c1_eb,
                                pE1, 1, pAIp, pAJp);
    node_kernel<<<100, 240>>>(x, c1_nw, c1_nb, pAIp, pAJp, pX1);

    // ---- layer 2 (e_out unused downstream -> skipped) ----
    pre_kernel<<<100, 256>>>(pX1, c2_sw, c2_sb, pPi, pPj);
    pair_kernel<<<pgrid, 256>>>(a, pE1, pPi, pPj, c2_sw,
                                c2_aiw, c2_aib, c2_ajw, c2_ajb, c2_ew, c2_eb,
                                nullptr, 0, pAIp, pAJp);
    node_kernel<<<100, 240>>>(pX1, c2_nw, c2_nb, pAIp, pAJp, pX2);

    // ---- dense head ----
    dim3 dgrid(50, 3);
    dense_kernel<<<dgrid, 480>>>(pX2, dw, db, out);
}